// round 1
// baseline (speedup 1.0000x reference)
#include <cuda_runtime.h>
#include <math.h>

#define S_LEN 2048
#define D_MODEL 1024
#define N_HEADS 16
#define HEAD_DIM 64
#define FFN_DIM 4096
#define N_LAYERS 4
#define IN_DIM 64
#define OUT_DIM 128
#define DOC_LEN 256
#define N_DOCS 8
#define WIN 128

// ---------------- scratch (no allocations allowed) ----------------
__device__ float g_h [S_LEN * D_MODEL];
__device__ float g_hn[S_LEN * D_MODEL];
__device__ float g_q [S_LEN * D_MODEL];
__device__ float g_k [S_LEN * D_MODEL];
__device__ float g_v [S_LEN * D_MODEL];
__device__ float g_att[S_LEN * D_MODEL];
__device__ float g_f1[S_LEN * FFN_DIM];
__device__ float g_f3[S_LEN * FFN_DIM];

// ---------------- generic SGEMM: C = A[M,K] @ B[K,N] (+bias) (+=) ----------
// Requirements: M % 128 == 0, N % 128 == 0, K % 16 == 0 (all shapes here comply)
template <bool ADD, bool BIAS>
__global__ __launch_bounds__(256)
void sgemm128(const float* __restrict__ A, const float* __restrict__ B,
              const float* __restrict__ bias, float* __restrict__ C,
              int M, int N, int K) {
    constexpr int BM = 128, BN = 128, BK = 16;
    __shared__ float As[BK][BM];
    __shared__ float Bs[BK][BN];

    const int tid = threadIdx.x;
    const int tx = tid & 15;       // 0..15 -> col block of 8
    const int ty = tid >> 4;       // 0..15 -> row block of 8
    const int rowBase = blockIdx.y * BM;
    const int colBase = blockIdx.x * BN;

    float acc[8][8];
#pragma unroll
    for (int i = 0; i < 8; i++)
#pragma unroll
        for (int j = 0; j < 8; j++) acc[i][j] = 0.f;

    for (int k0 = 0; k0 < K; k0 += BK) {
        // load A tile (128x16) and B tile (16x128), 512 float4 each
#pragma unroll
        for (int f = tid; f < 512; f += 256) {
            int ar = f >> 2;              // 0..127
            int ac = (f & 3) << 2;        // 0,4,8,12
            float4 va = *(const float4*)&A[(size_t)(rowBase + ar) * K + k0 + ac];
            As[ac + 0][ar] = va.x;
            As[ac + 1][ar] = va.y;
            As[ac + 2][ar] = va.z;
            As[ac + 3][ar] = va.w;

            int br = f >> 5;              // 0..15
            int bc = (f & 31) << 2;       // 0..124
            *(float4*)&Bs[br][bc] =
                *(const float4*)&B[(size_t)(k0 + br) * N + colBase + bc];
        }
        __syncthreads();

#pragma unroll
        for (int kk = 0; kk < BK; kk++) {
            float a[8], b[8];
            *(float4*)&a[0] = *(float4*)&As[kk][ty * 8];
            *(float4*)&a[4] = *(float4*)&As[kk][ty * 8 + 4];
            *(float4*)&b[0] = *(float4*)&Bs[kk][tx * 8];
            *(float4*)&b[4] = *(float4*)&Bs[kk][tx * 8 + 4];
#pragma unroll
            for (int i = 0; i < 8; i++)
#pragma unroll
                for (int j = 0; j < 8; j++) acc[i][j] += a[i] * b[j];
        }
        __syncthreads();
    }

    // epilogue
#pragma unroll
    for (int i = 0; i < 8; i++) {
        int row = rowBase + ty * 8 + i;
        float* Crow = C + (size_t)row * N + colBase + tx * 8;
#pragma unroll
        for (int j = 0; j < 8; j += 4) {
            float4 v;
            v.x = acc[i][j + 0];
            v.y = acc[i][j + 1];
            v.z = acc[i][j + 2];
            v.w = acc[i][j + 3];
            if (BIAS) {
                const float* bp = bias + colBase + tx * 8 + j;
                v.x += bp[0]; v.y += bp[1]; v.z += bp[2]; v.w += bp[3];
            }
            if (ADD) {
                float4 old = *(float4*)&Crow[j];
                v.x += old.x; v.y += old.y; v.z += old.z; v.w += old.w;
            }
            *(float4*)&Crow[j] = v;
        }
    }
}

// ---------------- RMSNorm: y = x * rsqrt(mean(x^2)+eps) * w ----------------
__global__ __launch_bounds__(256)
void rmsnorm_kernel(const float* __restrict__ x, const float* __restrict__ w,
                    float* __restrict__ y) {
    int row = blockIdx.x;
    const float* xr = x + (size_t)row * D_MODEL;
    float s = 0.f;
    for (int i = threadIdx.x; i < D_MODEL; i += 256) {
        float v = xr[i];
        s += v * v;
    }
    __shared__ float red[8];
#pragma unroll
    for (int o = 16; o; o >>= 1) s += __shfl_xor_sync(0xffffffffu, s, o);
    if ((threadIdx.x & 31) == 0) red[threadIdx.x >> 5] = s;
    __syncthreads();
    if (threadIdx.x < 8) {
        float t = red[threadIdx.x];
#pragma unroll
        for (int o = 4; o; o >>= 1) t += __shfl_xor_sync(0xffu, t, o);
        if (threadIdx.x == 0)
            red[0] = rsqrtf(t / (float)D_MODEL + 1e-5f);
    }
    __syncthreads();
    float r = red[0];
    float* yr = y + (size_t)row * D_MODEL;
    for (int i = threadIdx.x; i < D_MODEL; i += 256) yr[i] = xr[i] * r * w[i];
}

// ---------------- RoPE (in place on q and k) ----------------
__global__ __launch_bounds__(256)
void rope_kernel(float* __restrict__ q, float* __restrict__ k,
                 const int* __restrict__ tok_id) {
    int idx = blockIdx.x * 256 + threadIdx.x;   // S*H*32 = 1048576
    if (idx >= S_LEN * N_HEADS * (HEAD_DIM / 2)) return;
    int j = idx & 31;
    int h = (idx >> 5) & 15;
    int s = idx >> 9;
    float t = (float)tok_id[s];
    float inv = expf(-logf(10000.f) * (float)(2 * j) / (float)HEAD_DIM);
    float ang = t * inv;
    float c = cosf(ang), sn = sinf(ang);
    int base = s * D_MODEL + h * HEAD_DIM + j;
    float q1 = q[base], q2 = q[base + 32];
    q[base]      = q1 * c - q2 * sn;
    q[base + 32] = q1 * sn + q2 * c;
    float k1 = k[base], k2 = k[base + 32];
    k[base]      = k1 * c - k2 * sn;
    k[base + 32] = k1 * sn + k2 * c;
}

// ---------------- attention: block-diagonal (doc) windowed softmax --------
// grid: (N_DOCS, N_HEADS); block: 256 threads = 256 queries of one doc
__global__ __launch_bounds__(256)
void attention_kernel(const float* __restrict__ q, const float* __restrict__ k,
                      const float* __restrict__ v, float* __restrict__ out) {
    const int doc = blockIdx.x;
    const int head = blockIdx.y;
    const int qi = threadIdx.x;              // local token id == tok_id
    const int qg = doc * DOC_LEN + qi;

    __shared__ float Ks[64][64];
    __shared__ float Vs[64][64];

    float qreg[HEAD_DIM];
    const float scale = 0.125f;              // 1/sqrt(64)
    const float* qp = q + (size_t)qg * D_MODEL + head * HEAD_DIM;
#pragma unroll
    for (int d = 0; d < HEAD_DIM; d += 4) {
        float4 t = *(const float4*)&qp[d];
        qreg[d] = t.x * scale; qreg[d + 1] = t.y * scale;
        qreg[d + 2] = t.z * scale; qreg[d + 3] = t.w * scale;
    }

    float o[HEAD_DIM];
#pragma unroll
    for (int d = 0; d < HEAD_DIM; d++) o[d] = 0.f;
    float m = -1e30f, l = 0.f;

    for (int kt = 0; kt < 4; kt++) {
        __syncthreads();
        // load 64 rows of K and V (each 64x64 floats = 1024 float4)
        for (int f = threadIdx.x; f < 1024; f += 256) {
            int r = f >> 4;
            int c = (f & 15) << 2;
            int kg = doc * DOC_LEN + kt * 64 + r;
            *(float4*)&Ks[r][c] =
                *(const float4*)&k[(size_t)kg * D_MODEL + head * HEAD_DIM + c];
            *(float4*)&Vs[r][c] =
                *(const float4*)&v[(size_t)kg * D_MODEL + head * HEAD_DIM + c];
        }
        __syncthreads();

        for (int j = 0; j < 64; j++) {
            int tk = kt * 64 + j;           // key tok_id within doc
            int dlt = qi - tk;
            if (dlt < 0) dlt = -dlt;
            if (dlt < WIN) {
                float s = 0.f;
#pragma unroll
                for (int d = 0; d < HEAD_DIM; d++) s += qreg[d] * Ks[j][d];
                float mn = fmaxf(m, s);
                float corr = expf(m - mn);
                float p = expf(s - mn);
                l = l * corr + p;
#pragma unroll
                for (int d = 0; d < HEAD_DIM; d++)
                    o[d] = o[d] * corr + p * Vs[j][d];
                m = mn;
            }
        }
    }

    float invl = 1.f / l;
    float* op = out + (size_t)qg * D_MODEL + head * HEAD_DIM;
#pragma unroll
    for (int d = 0; d < HEAD_DIM; d += 4) {
        float4 t;
        t.x = o[d] * invl; t.y = o[d + 1] * invl;
        t.z = o[d + 2] * invl; t.w = o[d + 3] * invl;
        *(float4*)&op[d] = t;
    }
}

// ---------------- SwiGLU elementwise: f1 = silu(f1) * f3 ----------------
__global__ __launch_bounds__(256)
void silu_mul_kernel(float* __restrict__ f1, const float* __restrict__ f3,
                     int n) {
    int i = blockIdx.x * 256 + threadIdx.x;
    if (i < n) {
        float a = f1[i];
        f1[i] = (a / (1.f + expf(-a))) * f3[i];
    }
}

// ---------------- host orchestration ----------------
static void run_gemm(const float* A, const float* B, const float* bias,
                     float* C, int M, int N, int K, bool add, bool useBias) {
    dim3 grid(N / 128, M / 128);
    if (add)
        sgemm128<true, false><<<grid, 256>>>(A, B, nullptr, C, M, N, K);
    else if (useBias)
        sgemm128<false, true><<<grid, 256>>>(A, B, bias, C, M, N, K);
    else
        sgemm128<false, false><<<grid, 256>>>(A, B, nullptr, C, M, N, K);
}

extern "C" void kernel_launch(void* const* d_in, const int* in_sizes, int n_in,
                              void* d_out, int out_size) {
    const float* x          = (const float*)d_in[0];
    const float* emb_w      = (const float*)d_in[1];
    const float* emb_b      = (const float*)d_in[2];
    const float* wq         = (const float*)d_in[3];
    const float* wk         = (const float*)d_in[4];
    const float* wv         = (const float*)d_in[5];
    const float* wo         = (const float*)d_in[6];
    const float* attn_norm_w= (const float*)d_in[7];
    const float* ffn_norm_w = (const float*)d_in[8];
    const float* w1         = (const float*)d_in[9];
    const float* w2         = (const float*)d_in[10];
    const float* w3         = (const float*)d_in[11];
    const float* out_norm_w = (const float*)d_in[12];
    const float* out_w      = (const float*)d_in[13];
    const int*   tok_id     = (const int*)d_in[15];
    float* out = (float*)d_out;

    float *h, *hn, *q, *k, *v, *att, *f1, *f3;
    cudaGetSymbolAddress((void**)&h, g_h);
    cudaGetSymbolAddress((void**)&hn, g_hn);
    cudaGetSymbolAddress((void**)&q, g_q);
    cudaGetSymbolAddress((void**)&k, g_k);
    cudaGetSymbolAddress((void**)&v, g_v);
    cudaGetSymbolAddress((void**)&att, g_att);
    cudaGetSymbolAddress((void**)&f1, g_f1);
    cudaGetSymbolAddress((void**)&f3, g_f3);

    // embed: h = x @ emb_w + emb_b
    run_gemm(x, emb_w, emb_b, h, S_LEN, D_MODEL, IN_DIM, false, true);

    for (int l = 0; l < N_LAYERS; l++) {
        const float* wq_l = wq + (size_t)l * D_MODEL * D_MODEL;
        const float* wk_l = wk + (size_t)l * D_MODEL * D_MODEL;
        const float* wv_l = wv + (size_t)l * D_MODEL * D_MODEL;
        const float* wo_l = wo + (size_t)l * D_MODEL * D_MODEL;
        const float* w1_l = w1 + (size_t)l * D_MODEL * FFN_DIM;
        const float* w2_l = w2 + (size_t)l * FFN_DIM * D_MODEL;
        const float* w3_l = w3 + (size_t)l * D_MODEL * FFN_DIM;

        // attn norm
        rmsnorm_kernel<<<S_LEN, 256>>>(h, attn_norm_w + l * D_MODEL, hn);
        // q, k, v projections
        run_gemm(hn, wq_l, nullptr, q, S_LEN, D_MODEL, D_MODEL, false, false);
        run_gemm(hn, wk_l, nullptr, k, S_LEN, D_MODEL, D_MODEL, false, false);
        run_gemm(hn, wv_l, nullptr, v, S_LEN, D_MODEL, D_MODEL, false, false);
        // rope on q, k
        rope_kernel<<<(S_LEN * N_HEADS * 32) / 256, 256>>>(q, k, tok_id);
        // attention
        attention_kernel<<<dim3(N_DOCS, N_HEADS), 256>>>(q, k, v, att);
        // h += att @ wo
        run_gemm(att, wo_l, nullptr, h, S_LEN, D_MODEL, D_MODEL, true, false);
        // ffn norm
        rmsnorm_kernel<<<S_LEN, 256>>>(h, ffn_norm_w + l * D_MODEL, hn);
        // ffn
        run_gemm(hn, w1_l, nullptr, f1, S_LEN, FFN_DIM, D_MODEL, false, false);
        run_gemm(hn, w3_l, nullptr, f3, S_LEN, FFN_DIM, D_MODEL, false, false);
        silu_mul_kernel<<<(S_LEN * FFN_DIM) / 256, 256>>>(f1, f3,
                                                          S_LEN * FFN_DIM);
        // h += (silu(f1)*f3) @ w2
        run_gemm(f1, w2_l, nullptr, h, S_LEN, D_MODEL, FFN_DIM, true, false);
    }

    // final norm + head
    rmsnorm_kernel<<<S_LEN, 256>>>(h, out_norm_w, hn);
    run_gemm(hn, out_w, nullptr, out, S_LEN, OUT_DIM, D_MODEL, false, false);
}

// round 3
// speedup vs baseline: 1.4166x; 1.4166x over previous
#include <cuda_runtime.h>
#include <math.h>
#include <stdint.h>

#define S_LEN 2048
#define D_MODEL 1024
#define N_HEADS 16
#define HEAD_DIM 64
#define FFN_DIM 4096
#define N_LAYERS 4
#define IN_DIM 64
#define OUT_DIM 128
#define DOC_LEN 256
#define N_DOCS 8
#define WIN 128

// ---------------- scratch (no allocations allowed) ----------------
__device__ float g_h [S_LEN * D_MODEL];
__device__ float g_hn[S_LEN * D_MODEL];
__device__ float g_q [S_LEN * D_MODEL];
__device__ float g_k [S_LEN * D_MODEL];
__device__ float g_v [S_LEN * D_MODEL];
__device__ float g_att[S_LEN * D_MODEL];
__device__ float g_f1[S_LEN * FFN_DIM];
__device__ float g_f3[S_LEN * FFN_DIM];

// ================= 3xTF32 tensor-core GEMM (fp32-accurate) =================
// C[M,N] = A[M,K] @ B[K,N] (+bias) (+= C), M%128==0, N%128==0, K%16==0
// CTA tile 128x128x16, 8 warps (2x4), warp tile 64x32, mma.m16n8k8.tf32
// Each operand split hi/lo; acc += ah*bh + al*bh + ah*bl  (al*bl ~2^-22 dropped)

#define AS_STRIDE 20     // 16 + 4 pad (floats per A row)
#define BS_STRIDE 136    // 128 + 8 pad (floats per B row)
#define AS_TILE (128 * AS_STRIDE)
#define BS_TILE (16 * BS_STRIDE)

__device__ __forceinline__ uint32_t f2tf(float x) {
    uint32_t r;
    asm("cvt.rna.tf32.f32 %0, %1;" : "=r"(r) : "f"(x));
    return r;
}
__device__ __forceinline__ void split_tf32(float x, uint32_t& hi, uint32_t& lo) {
    hi = f2tf(x);
    lo = f2tf(x - __uint_as_float(hi));
}
__device__ __forceinline__ void cp_async16(uint32_t dst, const void* src) {
    asm volatile("cp.async.cg.shared.global [%0], [%1], 16;\n"
                 :: "r"(dst), "l"(src));
}
__device__ __forceinline__ void cp_commit() {
    asm volatile("cp.async.commit_group;\n");
}
template <int N_>
__device__ __forceinline__ void cp_wait() {
    asm volatile("cp.async.wait_group %0;\n" :: "n"(N_));
}
__device__ __forceinline__ void mma_tf32(float* d, const uint32_t* a,
                                         const uint32_t* b) {
    asm volatile(
        "mma.sync.aligned.m16n8k8.row.col.f32.tf32.tf32.f32 "
        "{%0,%1,%2,%3}, {%4,%5,%6,%7}, {%8,%9}, {%0,%1,%2,%3};\n"
        : "+f"(d[0]), "+f"(d[1]), "+f"(d[2]), "+f"(d[3])
        : "r"(a[0]), "r"(a[1]), "r"(a[2]), "r"(a[3]), "r"(b[0]), "r"(b[1]));
}

template <bool ADD, bool BIAS>
__device__ __forceinline__ void tgemm_core(const float* __restrict__ A,
                                           const float* __restrict__ B,
                                           const float* __restrict__ bias,
                                           float* __restrict__ C,
                                           int M, int N, int K) {
    __shared__ float As[2 * AS_TILE];
    __shared__ float Bs[2 * BS_TILE];

    const int tid = threadIdx.x;
    const int lane = tid & 31;
    const int w = tid >> 5;
    const int wm = w & 1;           // 0..1 -> 64-row slab
    const int wn = w >> 1;          // 0..3 -> 32-col slab
    const int rowBase = blockIdx.y * 128;
    const int colBase = blockIdx.x * 128;
    const int ac = lane & 3;
    const int lr = lane >> 2;

    const uint32_t sA0 = (uint32_t)__cvta_generic_to_shared(As);
    const uint32_t sB0 = (uint32_t)__cvta_generic_to_shared(Bs);

    const int am[2] = { (tid) >> 2, (tid + 256) >> 2 };
    const int aks = (tid & 3) << 2;
    const int bk[2] = { tid >> 5, (tid + 256) >> 5 };
    const int bns = (tid & 31) << 2;

    auto load_tiles = [&](int stage, int k0) {
        uint32_t sA = sA0 + stage * AS_TILE * 4;
        uint32_t sB = sB0 + stage * BS_TILE * 4;
#pragma unroll
        for (int t = 0; t < 2; t++) {
            cp_async16(sA + (am[t] * AS_STRIDE + aks) * 4,
                       A + (size_t)(rowBase + am[t]) * K + k0 + aks);
            cp_async16(sB + (bk[t] * BS_STRIDE + bns) * 4,
                       B + (size_t)(k0 + bk[t]) * N + colBase + bns);
        }
    };

    float acc[4][4][4];
#pragma unroll
    for (int i = 0; i < 4; i++)
#pragma unroll
        for (int j = 0; j < 4; j++)
#pragma unroll
            for (int t = 0; t < 4; t++) acc[i][j][t] = 0.f;

    const int iters = K >> 4;
    load_tiles(0, 0);
    cp_commit();

    for (int it = 0; it < iters; ++it) {
        if (it + 1 < iters) {
            load_tiles((it + 1) & 1, (it + 1) << 4);
            cp_commit();
            cp_wait<1>();
        } else {
            cp_wait<0>();
        }
        __syncthreads();

        const float* as = As + (it & 1) * AS_TILE;
        const float* bs = Bs + (it & 1) * BS_TILE;

#pragma unroll
        for (int kc = 0; kc < 16; kc += 8) {
            uint32_t ah[4][4], al[4][4], bh[4][2], bl[4][2];
#pragma unroll
            for (int i = 0; i < 4; i++) {
                int r = wm * 64 + i * 16 + lr;
                split_tf32(as[r * AS_STRIDE + kc + ac],        ah[i][0], al[i][0]);
                split_tf32(as[(r + 8) * AS_STRIDE + kc + ac],  ah[i][1], al[i][1]);
                split_tf32(as[r * AS_STRIDE + kc + ac + 4],    ah[i][2], al[i][2]);
                split_tf32(as[(r + 8) * AS_STRIDE + kc + ac + 4], ah[i][3], al[i][3]);
            }
#pragma unroll
            for (int j = 0; j < 4; j++) {
                int n = wn * 32 + j * 8 + lr;
                split_tf32(bs[(kc + ac) * BS_STRIDE + n],     bh[j][0], bl[j][0]);
                split_tf32(bs[(kc + ac + 4) * BS_STRIDE + n], bh[j][1], bl[j][1]);
            }
#pragma unroll
            for (int i = 0; i < 4; i++)
#pragma unroll
                for (int j = 0; j < 4; j++) {
                    mma_tf32(acc[i][j], al[i], bh[j]);
                    mma_tf32(acc[i][j], ah[i], bl[j]);
                    mma_tf32(acc[i][j], ah[i], bh[j]);
                }
        }
        __syncthreads();
    }

    // epilogue
#pragma unroll
    for (int i = 0; i < 4; i++) {
        int r0 = rowBase + wm * 64 + i * 16 + lr;
#pragma unroll
        for (int j = 0; j < 4; j++) {
            int c0 = colBase + wn * 32 + j * 8 + ac * 2;
            float2 v0 = make_float2(acc[i][j][0], acc[i][j][1]);
            float2 v1 = make_float2(acc[i][j][2], acc[i][j][3]);
            if (BIAS) {
                float b0 = bias[c0], b1 = bias[c0 + 1];
                v0.x += b0; v0.y += b1; v1.x += b0; v1.y += b1;
            }
            float* p0 = C + (size_t)r0 * N + c0;
            float* p1 = C + (size_t)(r0 + 8) * N + c0;
            if (ADD) {
                float2 o0 = *(float2*)p0, o1 = *(float2*)p1;
                v0.x += o0.x; v0.y += o0.y;
                v1.x += o1.x; v1.y += o1.y;
            }
            *(float2*)p0 = v0;
            *(float2*)p1 = v1;
        }
    }
}

template <bool ADD, bool BIAS>
__global__ __launch_bounds__(256)
void tgemm_kernel(const float* __restrict__ A, const float* __restrict__ B,
                  const float* __restrict__ bias, float* __restrict__ C,
                  int M, int N, int K) {
    tgemm_core<ADD, BIAS>(A, B, bias, C, M, N, K);
}

// fused QKV: blockIdx.z selects weight/output
__global__ __launch_bounds__(256)
void qkv_kernel(const float* __restrict__ hn, const float* __restrict__ wq,
                const float* __restrict__ wk, const float* __restrict__ wv,
                float* __restrict__ q, float* __restrict__ k,
                float* __restrict__ v) {
    const float* B = (blockIdx.z == 0) ? wq : (blockIdx.z == 1) ? wk : wv;
    float* C = (blockIdx.z == 0) ? q : (blockIdx.z == 1) ? k : v;
    tgemm_core<false, false>(hn, B, nullptr, C, S_LEN, D_MODEL, D_MODEL);
}

// fused W1 / W3: blockIdx.z selects
__global__ __launch_bounds__(256)
void w13_kernel(const float* __restrict__ hn, const float* __restrict__ w1,
                const float* __restrict__ w3, float* __restrict__ f1,
                float* __restrict__ f3) {
    const float* B = (blockIdx.z == 0) ? w1 : w3;
    float* C = (blockIdx.z == 0) ? f1 : f3;
    tgemm_core<false, false>(hn, B, nullptr, C, S_LEN, FFN_DIM, D_MODEL);
}

// ---------------- RMSNorm ----------------
__global__ __launch_bounds__(256)
void rmsnorm_kernel(const float* __restrict__ x, const float* __restrict__ w,
                    float* __restrict__ y) {
    int row = blockIdx.x;
    const float* xr = x + (size_t)row * D_MODEL;
    float s = 0.f;
    for (int i = threadIdx.x; i < D_MODEL; i += 256) {
        float v = xr[i];
        s += v * v;
    }
    __shared__ float red[8];
#pragma unroll
    for (int o = 16; o; o >>= 1) s += __shfl_xor_sync(0xffffffffu, s, o);
    if ((threadIdx.x & 31) == 0) red[threadIdx.x >> 5] = s;
    __syncthreads();
    if (threadIdx.x < 8) {
        float t = red[threadIdx.x];
#pragma unroll
        for (int o = 4; o; o >>= 1) t += __shfl_xor_sync(0xffu, t, o);
        if (threadIdx.x == 0) red[0] = rsqrtf(t / (float)D_MODEL + 1e-5f);
    }
    __syncthreads();
    float r = red[0];
    float* yr = y + (size_t)row * D_MODEL;
    for (int i = threadIdx.x; i < D_MODEL; i += 256) yr[i] = xr[i] * r * w[i];
}

// ---------------- RoPE (in place on q and k) ----------------
__global__ __launch_bounds__(256)
void rope_kernel(float* __restrict__ q, float* __restrict__ k,
                 const int* __restrict__ tok_id) {
    int idx = blockIdx.x * 256 + threadIdx.x;
    if (idx >= S_LEN * N_HEADS * (HEAD_DIM / 2)) return;
    int j = idx & 31;
    int h = (idx >> 5) & 15;
    int s = idx >> 9;
    float t = (float)tok_id[s];
    float inv = expf(-logf(10000.f) * (float)(2 * j) / (float)HEAD_DIM);
    float ang = t * inv;
    float c = cosf(ang), sn = sinf(ang);
    int base = s * D_MODEL + h * HEAD_DIM + j;
    float q1 = q[base], q2 = q[base + 32];
    q[base] = q1 * c - q2 * sn;
    q[base + 32] = q1 * sn + q2 * c;
    float k1 = k[base], k2 = k[base + 32];
    k[base] = k1 * c - k2 * sn;
    k[base + 32] = k1 * sn + k2 * c;
}

// ---------------- attention: block-diagonal (doc) windowed softmax --------
__global__ __launch_bounds__(256)
void attention_kernel(const float* __restrict__ q, const float* __restrict__ k,
                      const float* __restrict__ v, float* __restrict__ out) {
    const int doc = blockIdx.x;
    const int head = blockIdx.y;
    const int qi = threadIdx.x;
    const int qg = doc * DOC_LEN + qi;

    __shared__ float Ks[64][64];
    __shared__ float Vs[64][64];

    float qreg[HEAD_DIM];
    const float scale = 0.125f;
    const float* qp = q + (size_t)qg * D_MODEL + head * HEAD_DIM;
#pragma unroll
    for (int d = 0; d < HEAD_DIM; d += 4) {
        float4 t = *(const float4*)&qp[d];
        qreg[d] = t.x * scale; qreg[d + 1] = t.y * scale;
        qreg[d + 2] = t.z * scale; qreg[d + 3] = t.w * scale;
    }

    float o[HEAD_DIM];
#pragma unroll
    for (int d = 0; d < HEAD_DIM; d++) o[d] = 0.f;
    float m = -1e30f, l = 0.f;

    for (int kt = 0; kt < 4; kt++) {
        __syncthreads();
        for (int f = threadIdx.x; f < 1024; f += 256) {
            int r = f >> 4;
            int c = (f & 15) << 2;
            int kg = doc * DOC_LEN + kt * 64 + r;
            *(float4*)&Ks[r][c] =
                *(const float4*)&k[(size_t)kg * D_MODEL + head * HEAD_DIM + c];
            *(float4*)&Vs[r][c] =
                *(const float4*)&v[(size_t)kg * D_MODEL + head * HEAD_DIM + c];
        }
        __syncthreads();

        for (int j = 0; j < 64; j++) {
            int tk = kt * 64 + j;
            int dlt = qi - tk;
            if (dlt < 0) dlt = -dlt;
            if (dlt < WIN) {
                float s = 0.f;
#pragma unroll
                for (int d = 0; d < HEAD_DIM; d++) s += qreg[d] * Ks[j][d];
                float mn = fmaxf(m, s);
                float corr = expf(m - mn);
                float p = expf(s - mn);
                l = l * corr + p;
#pragma unroll
                for (int d = 0; d < HEAD_DIM; d++)
                    o[d] = o[d] * corr + p * Vs[j][d];
                m = mn;
            }
        }
    }

    float invl = 1.f / l;
    float* op = out + (size_t)qg * D_MODEL + head * HEAD_DIM;
#pragma unroll
    for (int d = 0; d < HEAD_DIM; d += 4) {
        float4 t;
        t.x = o[d] * invl; t.y = o[d + 1] * invl;
        t.z = o[d + 2] * invl; t.w = o[d + 3] * invl;
        *(float4*)&op[d] = t;
    }
}

// ---------------- SwiGLU elementwise: f1 = silu(f1) * f3 ----------------
__global__ __launch_bounds__(256)
void silu_mul_kernel(float* __restrict__ f1, const float* __restrict__ f3,
                     int n4) {
    int i = blockIdx.x * 256 + threadIdx.x;
    if (i < n4) {
        float4 a = ((const float4*)f1)[i];
        float4 b = ((const float4*)f3)[i];
        a.x = (a.x / (1.f + expf(-a.x))) * b.x;
        a.y = (a.y / (1.f + expf(-a.y))) * b.y;
        a.z = (a.z / (1.f + expf(-a.z))) * b.z;
        a.w = (a.w / (1.f + expf(-a.w))) * b.w;
        ((float4*)f1)[i] = a;
    }
}

// ---------------- host orchestration ----------------
extern "C" void kernel_launch(void* const* d_in, const int* in_sizes, int n_in,
                              void* d_out, int out_size) {
    const float* x           = (const float*)d_in[0];
    const float* emb_w       = (const float*)d_in[1];
    const float* emb_b       = (const float*)d_in[2];
    const float* wq          = (const float*)d_in[3];
    const float* wk          = (const float*)d_in[4];
    const float* wv          = (const float*)d_in[5];
    const float* wo          = (const float*)d_in[6];
    const float* attn_norm_w = (const float*)d_in[7];
    const float* ffn_norm_w  = (const float*)d_in[8];
    const float* w1          = (const float*)d_in[9];
    const float* w2          = (const float*)d_in[10];
    const float* w3          = (const float*)d_in[11];
    const float* out_norm_w  = (const float*)d_in[12];
    const float* out_w       = (const float*)d_in[13];
    const int*   tok_id      = (const int*)d_in[15];
    float* out = (float*)d_out;

    float *h, *hn, *q, *k, *v, *att, *f1, *f3;
    cudaGetSymbolAddress((void**)&h, g_h);
    cudaGetSymbolAddress((void**)&hn, g_hn);
    cudaGetSymbolAddress((void**)&q, g_q);
    cudaGetSymbolAddress((void**)&k, g_k);
    cudaGetSymbolAddress((void**)&v, g_v);
    cudaGetSymbolAddress((void**)&att, g_att);
    cudaGetSymbolAddress((void**)&f1, g_f1);
    cudaGetSymbolAddress((void**)&f3, g_f3);

    // embed: h = x @ emb_w + emb_b
    tgemm_kernel<false, true><<<dim3(D_MODEL / 128, S_LEN / 128), 256>>>(
        x, emb_w, emb_b, h, S_LEN, D_MODEL, IN_DIM);

    for (int l = 0; l < N_LAYERS; l++) {
        const float* wq_l = wq + (size_t)l * D_MODEL * D_MODEL;
        const float* wk_l = wk + (size_t)l * D_MODEL * D_MODEL;
        const float* wv_l = wv + (size_t)l * D_MODEL * D_MODEL;
        const float* wo_l = wo + (size_t)l * D_MODEL * D_MODEL;
        const float* w1_l = w1 + (size_t)l * D_MODEL * FFN_DIM;
        const float* w2_l = w2 + (size_t)l * FFN_DIM * D_MODEL;
        const float* w3_l = w3 + (size_t)l * D_MODEL * FFN_DIM;

        rmsnorm_kernel<<<S_LEN, 256>>>(h, attn_norm_w + l * D_MODEL, hn);

        qkv_kernel<<<dim3(D_MODEL / 128, S_LEN / 128, 3), 256>>>(
            hn, wq_l, wk_l, wv_l, q, k, v);

        rope_kernel<<<(S_LEN * N_HEADS * 32) / 256, 256>>>(q, k, tok_id);

        attention_kernel<<<dim3(N_DOCS, N_HEADS), 256>>>(q, k, v, att);

        tgemm_kernel<true, false><<<dim3(D_MODEL / 128, S_LEN / 128), 256>>>(
            att, wo_l, nullptr, h, S_LEN, D_MODEL, D_MODEL);

        rmsnorm_kernel<<<S_LEN, 256>>>(h, ffn_norm_w + l * D_MODEL, hn);

        w13_kernel<<<dim3(FFN_DIM / 128, S_LEN / 128, 2), 256>>>(
            hn, w1_l, w3_l, f1, f3);

        silu_mul_kernel<<<(S_LEN * FFN_DIM / 4) / 256, 256>>>(
            f1, f3, S_LEN * FFN_DIM / 4);

        tgemm_kernel<true, false><<<dim3(D_MODEL / 128, S_LEN / 128), 256>>>(
            f1, w2_l, nullptr, h, S_LEN, D_MODEL, FFN_DIM);
    }

    rmsnorm_kernel<<<S_LEN, 256>>>(h, out_norm_w, hn);
    tgemm_kernel<false, false><<<dim3(OUT_DIM / 128, S_LEN / 128), 256>>>(
        hn, out_w, nullptr, out, S_LEN, OUT_DIM, D_MODEL);
}

// round 4
// speedup vs baseline: 1.8397x; 1.2987x over previous
#include <cuda_runtime.h>
#include <cuda_bf16.h>
#include <math.h>
#include <stdint.h>

#define S_LEN 2048
#define D_MODEL 1024
#define N_HEADS 16
#define HEAD_DIM 64
#define FFN_DIM 4096
#define N_LAYERS 4
#define IN_DIM 64
#define OUT_DIM 128
#define DOC_LEN 256
#define N_DOCS 8
#define WIN 128

// ---------------- scratch (no allocations allowed) ----------------
__device__ float g_h [S_LEN * D_MODEL];
__device__ float g_hn[S_LEN * D_MODEL];
__device__ float g_q [S_LEN * D_MODEL];
__device__ float g_k [S_LEN * D_MODEL];
__device__ float g_v [S_LEN * D_MODEL];
__device__ float g_att[S_LEN * D_MODEL];
__device__ float g_f1[S_LEN * FFN_DIM];
__device__ float g_f3[S_LEN * FFN_DIM];

// ============== bf16-split (hi+lo) tensor-core GEMM ==============
// C[M,N] = A[M,K] @ B[K,N] (+bias) (+= C); M%128==0, N%128==0, K%16==0.
// CTA tile 128x128x16, 8 warps (2x4), warp tile 64x32, mma.m16n8k16.bf16.
// Each fp32 split hi/lo bf16 at smem-store time into separate u16 planes;
// B stored transposed [n][k] so all consumer fragment loads are LDS.32.
// acc += al*bh + ah*bl + ah*bh  (dropped terms ~2^-18).
// Row pad: 24 u16 = 12 words -> conflict-free LDS/STS (12*lr mod 32 spacing 4).

#define RW 12   // words per 16-element row (16 u16 data + 8 u16 pad)

__device__ __forceinline__ void bsplit(float x, uint16_t& h, uint16_t& l) {
    __nv_bfloat16 hb = __float2bfloat16_rn(x);
    float hf = __bfloat162float(hb);
    __nv_bfloat16 lb = __float2bfloat16_rn(x - hf);
    h = __bfloat16_as_ushort(hb);
    l = __bfloat16_as_ushort(lb);
}

__device__ __forceinline__ void mma_bf16(float* d, const uint32_t* a,
                                         const uint32_t* b) {
    asm volatile(
        "mma.sync.aligned.m16n8k16.row.col.f32.bf16.bf16.f32 "
        "{%0,%1,%2,%3}, {%4,%5,%6,%7}, {%8,%9}, {%0,%1,%2,%3};\n"
        : "+f"(d[0]), "+f"(d[1]), "+f"(d[2]), "+f"(d[3])
        : "r"(a[0]), "r"(a[1]), "r"(a[2]), "r"(a[3]), "r"(b[0]), "r"(b[1]));
}

template <bool ADD, bool BIAS>
__device__ __forceinline__ void tgemm_core(const float* __restrict__ A,
                                           const float* __restrict__ B,
                                           const float* __restrict__ bias,
                                           float* __restrict__ C,
                                           int M, int N, int K) {
    // 4 planes x 2 stages x 128 rows x 12 words = 48KB total
    __shared__ uint32_t AsH[2][128 * RW];
    __shared__ uint32_t AsL[2][128 * RW];
    __shared__ uint32_t BsH[2][128 * RW];   // transposed: [n][k]
    __shared__ uint32_t BsL[2][128 * RW];

    const int tid = threadIdx.x;
    const int lane = tid & 31;
    const int w = tid >> 5;
    const int wm = w & 1;            // 64-row slab
    const int wn = w >> 1;           // 32-col slab
    const int rowBase = blockIdx.y * 128;
    const int colBase = blockIdx.x * 128;
    const int ac = lane & 3;
    const int lr = lane >> 2;

    // producer mapping: thread owns one A row-segment and one B column-segment
    const int prow = tid & 127;          // A row / B col (local)
    const int pk = (tid >> 7) * 8;       // k sub-range base (0 or 8)

    const float* Ap = A + (size_t)(rowBase + prow) * K + pk;
    const float* Bp = B + (size_t)pk * N + colBase + prow;

    float4 a0r, a1r;
    float br[8];

    auto ldg_tiles = [&](int k0) {
        const float* ap = Ap + k0;
        a0r = *(const float4*)ap;
        a1r = *(const float4*)(ap + 4);
        const float* bp = Bp + (size_t)k0 * N;
#pragma unroll
        for (int i = 0; i < 8; i++) br[i] = bp[(size_t)i * N];
    };

    auto sts_tiles = [&](int stage) {
        uint16_t h[8], l[8];
        bsplit(a0r.x, h[0], l[0]); bsplit(a0r.y, h[1], l[1]);
        bsplit(a0r.z, h[2], l[2]); bsplit(a0r.w, h[3], l[3]);
        bsplit(a1r.x, h[4], l[4]); bsplit(a1r.y, h[5], l[5]);
        bsplit(a1r.z, h[6], l[6]); bsplit(a1r.w, h[7], l[7]);
        uint4 hw, lw;
        hw.x = (uint32_t)h[0] | ((uint32_t)h[1] << 16);
        hw.y = (uint32_t)h[2] | ((uint32_t)h[3] << 16);
        hw.z = (uint32_t)h[4] | ((uint32_t)h[5] << 16);
        hw.w = (uint32_t)h[6] | ((uint32_t)h[7] << 16);
        lw.x = (uint32_t)l[0] | ((uint32_t)l[1] << 16);
        lw.y = (uint32_t)l[2] | ((uint32_t)l[3] << 16);
        lw.z = (uint32_t)l[4] | ((uint32_t)l[5] << 16);
        lw.w = (uint32_t)l[6] | ((uint32_t)l[7] << 16);
        int wo = prow * RW + (pk >> 1);
        *(uint4*)&AsH[stage][wo] = hw;
        *(uint4*)&AsL[stage][wo] = lw;

#pragma unroll
        for (int i = 0; i < 8; i++) bsplit(br[i], h[i], l[i]);
        hw.x = (uint32_t)h[0] | ((uint32_t)h[1] << 16);
        hw.y = (uint32_t)h[2] | ((uint32_t)h[3] << 16);
        hw.z = (uint32_t)h[4] | ((uint32_t)h[5] << 16);
        hw.w = (uint32_t)h[6] | ((uint32_t)h[7] << 16);
        lw.x = (uint32_t)l[0] | ((uint32_t)l[1] << 16);
        lw.y = (uint32_t)l[2] | ((uint32_t)l[3] << 16);
        lw.z = (uint32_t)l[4] | ((uint32_t)l[5] << 16);
        lw.w = (uint32_t)l[6] | ((uint32_t)l[7] << 16);
        *(uint4*)&BsH[stage][wo] = hw;
        *(uint4*)&BsL[stage][wo] = lw;
    };

    float acc[4][4][4];
#pragma unroll
    for (int i = 0; i < 4; i++)
#pragma unroll
        for (int j = 0; j < 4; j++)
#pragma unroll
            for (int t = 0; t < 4; t++) acc[i][j][t] = 0.f;

    const int iters = K >> 4;
    ldg_tiles(0);
    sts_tiles(0);

    for (int it = 0; it < iters; ++it) {
        __syncthreads();
        if (it + 1 < iters) ldg_tiles((it + 1) << 4);

        const int st = it & 1;
        const uint32_t* ash = AsH[st];
        const uint32_t* asl = AsL[st];
        const uint32_t* bsh = BsH[st];
        const uint32_t* bsl = BsL[st];

        uint32_t bh[4][2], bl[4][2];
#pragma unroll
        for (int j = 0; j < 4; j++) {
            int n = wn * 32 + j * 8 + lr;
            int w0 = n * RW + ac;
            bh[j][0] = bsh[w0]; bh[j][1] = bsh[w0 + 4];
            bl[j][0] = bsl[w0]; bl[j][1] = bsl[w0 + 4];
        }
#pragma unroll
        for (int i = 0; i < 4; i++) {
            int r = wm * 64 + i * 16 + lr;
            int w0 = r * RW + ac;
            int w1 = (r + 8) * RW + ac;
            uint32_t ah[4] = { ash[w0], ash[w1], ash[w0 + 4], ash[w1 + 4] };
            uint32_t al[4] = { asl[w0], asl[w1], asl[w0 + 4], asl[w1 + 4] };
#pragma unroll
            for (int j = 0; j < 4; j++) {
                mma_bf16(acc[i][j], al, bh[j]);
                mma_bf16(acc[i][j], ah, bl[j]);
                mma_bf16(acc[i][j], ah, bh[j]);
            }
        }
        if (it + 1 < iters) sts_tiles((it + 1) & 1);
    }

    // epilogue (m16n8 f32 acc layout: c0,c1 @ (lr, 2ac..); c2,c3 @ (lr+8, ..))
#pragma unroll
    for (int i = 0; i < 4; i++) {
        int r0 = rowBase + wm * 64 + i * 16 + lr;
#pragma unroll
        for (int j = 0; j < 4; j++) {
            int c0 = colBase + wn * 32 + j * 8 + ac * 2;
            float2 v0 = make_float2(acc[i][j][0], acc[i][j][1]);
            float2 v1 = make_float2(acc[i][j][2], acc[i][j][3]);
            if (BIAS) {
                float b0 = bias[c0], b1 = bias[c0 + 1];
                v0.x += b0; v0.y += b1; v1.x += b0; v1.y += b1;
            }
            float* p0 = C + (size_t)r0 * N + c0;
            float* p1 = C + (size_t)(r0 + 8) * N + c0;
            if (ADD) {
                float2 o0 = *(float2*)p0, o1 = *(float2*)p1;
                v0.x += o0.x; v0.y += o0.y;
                v1.x += o1.x; v1.y += o1.y;
            }
            *(float2*)p0 = v0;
            *(float2*)p1 = v1;
        }
    }
}

template <bool ADD, bool BIAS>
__global__ __launch_bounds__(256)
void tgemm_kernel(const float* __restrict__ A, const float* __restrict__ B,
                  const float* __restrict__ bias, float* __restrict__ C,
                  int M, int N, int K) {
    tgemm_core<ADD, BIAS>(A, B, bias, C, M, N, K);
}

// fused QKV: blockIdx.z selects weight/output
__global__ __launch_bounds__(256)
void qkv_kernel(const float* __restrict__ hn, const float* __restrict__ wq,
                const float* __restrict__ wk, const float* __restrict__ wv,
                float* __restrict__ q, float* __restrict__ k,
                float* __restrict__ v) {
    const float* B = (blockIdx.z == 0) ? wq : (blockIdx.z == 1) ? wk : wv;
    float* C = (blockIdx.z == 0) ? q : (blockIdx.z == 1) ? k : v;
    tgemm_core<false, false>(hn, B, nullptr, C, S_LEN, D_MODEL, D_MODEL);
}

// fused W1 / W3: blockIdx.z selects
__global__ __launch_bounds__(256)
void w13_kernel(const float* __restrict__ hn, const float* __restrict__ w1,
                const float* __restrict__ w3, float* __restrict__ f1,
                float* __restrict__ f3) {
    const float* B = (blockIdx.z == 0) ? w1 : w3;
    float* C = (blockIdx.z == 0) ? f1 : f3;
    tgemm_core<false, false>(hn, B, nullptr, C, S_LEN, FFN_DIM, D_MODEL);
}

// ---------------- RMSNorm ----------------
__global__ __launch_bounds__(256)
void rmsnorm_kernel(const float* __restrict__ x, const float* __restrict__ w,
                    float* __restrict__ y) {
    int row = blockIdx.x;
    const float* xr = x + (size_t)row * D_MODEL;
    float s = 0.f;
    for (int i = threadIdx.x; i < D_MODEL; i += 256) {
        float v = xr[i];
        s += v * v;
    }
    __shared__ float red[8];
#pragma unroll
    for (int o = 16; o; o >>= 1) s += __shfl_xor_sync(0xffffffffu, s, o);
    if ((threadIdx.x & 31) == 0) red[threadIdx.x >> 5] = s;
    __syncthreads();
    if (threadIdx.x < 8) {
        float t = red[threadIdx.x];
#pragma unroll
        for (int o = 4; o; o >>= 1) t += __shfl_xor_sync(0xffu, t, o);
        if (threadIdx.x == 0) red[0] = rsqrtf(t / (float)D_MODEL + 1e-5f);
    }
    __syncthreads();
    float r = red[0];
    float* yr = y + (size_t)row * D_MODEL;
    for (int i = threadIdx.x; i < D_MODEL; i += 256) yr[i] = xr[i] * r * w[i];
}

// ---------------- RoPE (in place on q and k) ----------------
__global__ __launch_bounds__(256)
void rope_kernel(float* __restrict__ q, float* __restrict__ k,
                 const int* __restrict__ tok_id) {
    int idx = blockIdx.x * 256 + threadIdx.x;
    if (idx >= S_LEN * N_HEADS * (HEAD_DIM / 2)) return;
    int j = idx & 31;
    int h = (idx >> 5) & 15;
    int s = idx >> 9;
    float t = (float)tok_id[s];
    float inv = expf(-logf(10000.f) * (float)(2 * j) / (float)HEAD_DIM);
    float ang = t * inv;
    float c = cosf(ang), sn = sinf(ang);
    int base = s * D_MODEL + h * HEAD_DIM + j;
    float q1 = q[base], q2 = q[base + 32];
    q[base] = q1 * c - q2 * sn;
    q[base + 32] = q1 * sn + q2 * c;
    float k1 = k[base], k2 = k[base + 32];
    k[base] = k1 * c - k2 * sn;
    k[base + 32] = k1 * sn + k2 * c;
}

// ---------------- attention: block-diagonal (doc) windowed softmax --------
__global__ __launch_bounds__(256)
void attention_kernel(const float* __restrict__ q, const float* __restrict__ k,
                      const float* __restrict__ v, float* __restrict__ out) {
    const int doc = blockIdx.x;
    const int head = blockIdx.y;
    const int qi = threadIdx.x;
    const int qg = doc * DOC_LEN + qi;

    __shared__ float Ks[64][64];
    __shared__ float Vs[64][64];

    float qreg[HEAD_DIM];
    const float scale = 0.125f;
    const float* qp = q + (size_t)qg * D_MODEL + head * HEAD_DIM;
#pragma unroll
    for (int d = 0; d < HEAD_DIM; d += 4) {
        float4 t = *(const float4*)&qp[d];
        qreg[d] = t.x * scale; qreg[d + 1] = t.y * scale;
        qreg[d + 2] = t.z * scale; qreg[d + 3] = t.w * scale;
    }

    float o[HEAD_DIM];
#pragma unroll
    for (int d = 0; d < HEAD_DIM; d++) o[d] = 0.f;
    float m = -1e30f, l = 0.f;

    for (int kt = 0; kt < 4; kt++) {
        __syncthreads();
        for (int f = threadIdx.x; f < 1024; f += 256) {
            int r = f >> 4;
            int c = (f & 15) << 2;
            int kg = doc * DOC_LEN + kt * 64 + r;
            *(float4*)&Ks[r][c] =
                *(const float4*)&k[(size_t)kg * D_MODEL + head * HEAD_DIM + c];
            *(float4*)&Vs[r][c] =
                *(const float4*)&v[(size_t)kg * D_MODEL + head * HEAD_DIM + c];
        }
        __syncthreads();

        for (int j = 0; j < 64; j++) {
            int tk = kt * 64 + j;
            int dlt = qi - tk;
            if (dlt < 0) dlt = -dlt;
            if (dlt < WIN) {
                float s = 0.f;
#pragma unroll
                for (int d = 0; d < HEAD_DIM; d++) s += qreg[d] * Ks[j][d];
                float mn = fmaxf(m, s);
                float corr = expf(m - mn);
                float p = expf(s - mn);
                l = l * corr + p;
#pragma unroll
                for (int d = 0; d < HEAD_DIM; d++)
                    o[d] = o[d] * corr + p * Vs[j][d];
                m = mn;
            }
        }
    }

    float invl = 1.f / l;
    float* op = out + (size_t)qg * D_MODEL + head * HEAD_DIM;
#pragma unroll
    for (int d = 0; d < HEAD_DIM; d += 4) {
        float4 t;
        t.x = o[d] * invl; t.y = o[d + 1] * invl;
        t.z = o[d + 2] * invl; t.w = o[d + 3] * invl;
        *(float4*)&op[d] = t;
    }
}

// ---------------- SwiGLU elementwise: f1 = silu(f1) * f3 ----------------
__global__ __launch_bounds__(256)
void silu_mul_kernel(float* __restrict__ f1, const float* __restrict__ f3,
                     int n4) {
    int i = blockIdx.x * 256 + threadIdx.x;
    if (i < n4) {
        float4 a = ((const float4*)f1)[i];
        float4 b = ((const float4*)f3)[i];
        a.x = (a.x / (1.f + expf(-a.x))) * b.x;
        a.y = (a.y / (1.f + expf(-a.y))) * b.y;
        a.z = (a.z / (1.f + expf(-a.z))) * b.z;
        a.w = (a.w / (1.f + expf(-a.w))) * b.w;
        ((float4*)f1)[i] = a;
    }
}

// ---------------- host orchestration ----------------
extern "C" void kernel_launch(void* const* d_in, const int* in_sizes, int n_in,
                              void* d_out, int out_size) {
    const float* x           = (const float*)d_in[0];
    const float* emb_w       = (const float*)d_in[1];
    const float* emb_b       = (const float*)d_in[2];
    const float* wq          = (const float*)d_in[3];
    const float* wk          = (const float*)d_in[4];
    const float* wv          = (const float*)d_in[5];
    const float* wo          = (const float*)d_in[6];
    const float* attn_norm_w = (const float*)d_in[7];
    const float* ffn_norm_w  = (const float*)d_in[8];
    const float* w1          = (const float*)d_in[9];
    const float* w2          = (const float*)d_in[10];
    const float* w3          = (const float*)d_in[11];
    const float* out_norm_w  = (const float*)d_in[12];
    const float* out_w       = (const float*)d_in[13];
    const int*   tok_id      = (const int*)d_in[15];
    float* out = (float*)d_out;

    float *h, *hn, *q, *k, *v, *att, *f1, *f3;
    cudaGetSymbolAddress((void**)&h, g_h);
    cudaGetSymbolAddress((void**)&hn, g_hn);
    cudaGetSymbolAddress((void**)&q, g_q);
    cudaGetSymbolAddress((void**)&k, g_k);
    cudaGetSymbolAddress((void**)&v, g_v);
    cudaGetSymbolAddress((void**)&att, g_att);
    cudaGetSymbolAddress((void**)&f1, g_f1);
    cudaGetSymbolAddress((void**)&f3, g_f3);

    // embed: h = x @ emb_w + emb_b
    tgemm_kernel<false, true><<<dim3(D_MODEL / 128, S_LEN / 128), 256>>>(
        x, emb_w, emb_b, h, S_LEN, D_MODEL, IN_DIM);

    for (int l = 0; l < N_LAYERS; l++) {
        const float* wq_l = wq + (size_t)l * D_MODEL * D_MODEL;
        const float* wk_l = wk + (size_t)l * D_MODEL * D_MODEL;
        const float* wv_l = wv + (size_t)l * D_MODEL * D_MODEL;
        const float* wo_l = wo + (size_t)l * D_MODEL * D_MODEL;
        const float* w1_l = w1 + (size_t)l * D_MODEL * FFN_DIM;
        const float* w2_l = w2 + (size_t)l * FFN_DIM * D_MODEL;
        const float* w3_l = w3 + (size_t)l * D_MODEL * FFN_DIM;

        rmsnorm_kernel<<<S_LEN, 256>>>(h, attn_norm_w + l * D_MODEL, hn);

        qkv_kernel<<<dim3(D_MODEL / 128, S_LEN / 128, 3), 256>>>(
            hn, wq_l, wk_l, wv_l, q, k, v);

        rope_kernel<<<(S_LEN * N_HEADS * 32) / 256, 256>>>(q, k, tok_id);

        attention_kernel<<<dim3(N_DOCS, N_HEADS), 256>>>(q, k, v, att);

        tgemm_kernel<true, false><<<dim3(D_MODEL / 128, S_LEN / 128), 256>>>(
            att, wo_l, nullptr, h, S_LEN, D_MODEL, D_MODEL);

        rmsnorm_kernel<<<S_LEN, 256>>>(h, ffn_norm_w + l * D_MODEL, hn);

        w13_kernel<<<dim3(FFN_DIM / 128, S_LEN / 128, 2), 256>>>(
            hn, w1_l, w3_l, f1, f3);

        silu_mul_kernel<<<(S_LEN * FFN_DIM / 4) / 256, 256>>>(
            f1, f3, S_LEN * FFN_DIM / 4);

        tgemm_kernel<true, false><<<dim3(D_MODEL / 128, S_LEN / 128), 256>>>(
            f1, w2_l, nullptr, h, S_LEN, D_MODEL, FFN_DIM);
    }

    rmsnorm_kernel<<<S_LEN, 256>>>(h, out_norm_w, hn);
    tgemm_kernel<false, false><<<dim3(OUT_DIM / 128, S_LEN / 128), 256>>>(
        hn, out_w, nullptr, out, S_LEN, OUT_DIM, D_MODEL);
}